// round 11
// baseline (speedup 1.0000x reference)
#include <cuda_runtime.h>
#include <cuda_fp16.h>
#include <cstdint>

#define BATCH 32
#define HH 512
#define WW 512
#define NPX (BATCH * HH * WW)

#define TX 64   // final tile width
#define TY 32   // final tile height
#define SW1 80  // m/q region width  (TX + 16)
#define SH1 48  // m/q region height (TY + 16)
#define SW2 72  // s2 region width   (TX + 8)
#define SH2 40  // s2 region height  (TY + 8)

// 9x9 kernel weights in constant bank
__constant__ float c_w[81];

// Scratch (device globals: allocation-free per harness rules)
__device__ __half g_lm[NPX];   // local mean, fp16
__device__ __half g_sig[NPX];  // sigma, fp16
__device__ float  g_part[BATCH * 128];

typedef unsigned long long u64;

// --- f32x2 packed-math helpers (Blackwell FFMA2 path) ----------------------
__device__ __forceinline__ u64 bcast2(float w) {
    u64 r;
    asm("mov.b64 %0, {%1, %1};" : "=l"(r) : "r"(__float_as_uint(w)));
    return r;
}
__device__ __forceinline__ void fma2(u64& acc, u64 a, u64 b) {
    asm("fma.rn.f32x2 %0, %1, %2, %0;" : "+l"(acc) : "l"(a), "l"(b));
}
// {lo = hi32(a), hi = lo32(b)} : odd-tap pair from two aligned pairs (MOVs)
__device__ __forceinline__ u64 pair_merge(u64 a, u64 b) {
    u64 r;
    asm("mov.b64 %0, {%1, %2};"
        : "=l"(r) : "r"((uint32_t)(a >> 32)), "r"((uint32_t)b));
    return r;
}

// ---------------------------------------------------------------------------
// Blur core (double-pair register scheme), templated on smem row width.
// One call = 2 adjacent cols (pair pc) x 4 out rows (r0..r0+3), reading a
// 12-row window of aligned conflict-free LDS.64; odd taps via register merge.
// ---------------------------------------------------------------------------
template <int SWD>
__device__ __forceinline__ void blurT(const float* sm, int pc, int r0,
                                      u64 acc[4]) {
#pragma unroll
    for (int i = 0; i < 4; i++) acc[i] = 0ull;

    const u64* b64 = (const u64*)sm + r0 * (SWD / 2) + pc;

    u64 cur0[12], cur1[12];
#pragma unroll
    for (int j = 0; j < 12; j++) cur0[j] = b64[j * (SWD / 2)];

#pragma unroll
    for (int p = 0; p < 4; p++) {
#pragma unroll
        for (int ky = 0; ky < 9; ky++) {
            u64 we = bcast2(c_w[ky * 9 + 2 * p]);
#pragma unroll
            for (int oy = 0; oy < 4; oy++) fma2(acc[oy], we, cur0[ky + oy]);
        }
#pragma unroll
        for (int j = 0; j < 12; j++) cur1[j] = b64[j * (SWD / 2) + p + 1];
#pragma unroll
        for (int j = 0; j < 12; j++) cur0[j] = pair_merge(cur0[j], cur1[j]);
#pragma unroll
        for (int ky = 0; ky < 9; ky++) {
            u64 wo = bcast2(c_w[ky * 9 + 2 * p + 1]);
#pragma unroll
            for (int oy = 0; oy < 4; oy++) fma2(acc[oy], wo, cur0[ky + oy]);
        }
#pragma unroll
        for (int j = 0; j < 12; j++) cur0[j] = cur1[j];
    }
#pragma unroll
    for (int ky = 0; ky < 9; ky++) {
        u64 we = bcast2(c_w[ky * 9 + 8]);
#pragma unroll
        for (int oy = 0; oy < 4; oy++) fma2(acc[oy], we, cur0[ky + oy]);
    }
}

// ---------------------------------------------------------------------------
// Fused kernel: per 64x32 tile,
//   1) fill m (f32) + q (fp16) on 80x48 halo region from x (3x LDG.128 / 4px)
//   2) blur1 on 72x40 (360 slots over 256 threads): lm -> write g_lm (inner),
//      s2 = q - 2*lm*m + lm^2 (zeroed outside image) -> SMEM ONLY
//   3) blur2 on 64x32: sigma = sqrt(blur(s2)) -> g_sig + per-tile partials
// s2 never touches DRAM; one launch instead of two.
// smem: m 15360 + q 7680 + s2 11520 = 34560 B dynamic -> 4 CTA/SM.
// ---------------------------------------------------------------------------
__global__ __launch_bounds__(256, 4) void k_fused(const float* __restrict__ x) {
    extern __shared__ float dsm[];
    float*  sm1 = dsm;                            // [48][80] f32 m
    __half* sq1 = (__half*)(dsm + SH1 * SW1);     // [48][80] fp16 q
    float*  s2s = dsm + SH1 * SW1 + SH1 * SW1 / 2;  // [40][72] f32 s2
    __shared__ float warpsum[8];

    const int b = blockIdx.z;
    const int x0 = blockIdx.x * TX, y0 = blockIdx.y * TY;
    const int tid = threadIdx.y * 32 + threadIdx.x;
    const float inv3 = 1.f / 3.f;

    // ---- 1) fill m/q on 80x48 (960 4-px groups) ---------------------------
    {
        int r = tid / 20, c = tid - r * 20;
        for (int g = tid; g < 960; g += 256) {
            int gy = y0 - 8 + r, gx = x0 - 8 + 4 * c;
            float m0 = 0, m1 = 0, m2 = 0, m3 = 0;
            float q0 = 0, q1 = 0, q2 = 0, q3 = 0;
            if ((unsigned)gy < (unsigned)HH && (unsigned)gx < (unsigned)WW) {
                const float4* p =
                    (const float4*)(x + ((size_t)(b * HH + gy) * WW + gx) * 3);
                float4 A = __ldcs(p), B = __ldcs(p + 1), C = __ldcs(p + 2);
                m0 = (A.x + A.y + A.z) * inv3;
                m1 = (A.w + B.x + B.y) * inv3;
                m2 = (B.z + B.w + C.x) * inv3;
                m3 = (C.y + C.z + C.w) * inv3;
                q0 = fmaf(A.x, A.x, fmaf(A.y, A.y, A.z * A.z)) * inv3;
                q1 = fmaf(A.w, A.w, fmaf(B.x, B.x, B.y * B.y)) * inv3;
                q2 = fmaf(B.z, B.z, fmaf(B.w, B.w, C.x * C.x)) * inv3;
                q3 = fmaf(C.y, C.y, fmaf(C.z, C.z, C.w * C.w)) * inv3;
            }
            int i = r * SW1 + 4 * c;
            *(float4*)&sm1[i] = make_float4(m0, m1, m2, m3);
            __half2 qa = __floats2half2_rn(q0, q1);
            __half2 qb = __floats2half2_rn(q2, q3);
            *(uint2*)&sq1[i] = make_uint2(*(uint32_t*)&qa, *(uint32_t*)&qb);
            c += 16; r += 12;                 // 256 = 12*20 + 16
            if (c >= 20) { c -= 20; r += 1; }
        }
    }
    __syncthreads();

    // ---- 2) blur1 over 72x40 s2 region: 36 pair-cols x 10 row-groups ------
    for (int s = tid; s < 360; s += 256) {
        int rg = s / 36;
        int pc = s - rg * 36;

        u64 acc[4];
        blurT<SW1>(sm1, pc, 4 * rg, acc);

        bool wr = (pc >= 2) & (pc < 34) & (rg >= 1) & (rg < 9);
#pragma unroll
        for (int oy = 0; oy < 4; oy++) {
            float lm0 = __uint_as_float((uint32_t)acc[oy]);
            float lm1 = __uint_as_float((uint32_t)(acc[oy] >> 32));
            int rm = 4 * rg + oy;                 // s2-local row
            int mi = (rm + 4) * SW1 + 2 * pc + 4; // m/q center
            float2 mm = *(const float2*)&sm1[mi];
            float2 qq = __half22float2(*(const __half2*)&sq1[mi]);
            float s20 = fmaxf(fmaf(lm0, fmaf(-2.f, mm.x, lm0), qq.x), 0.f);
            float s21 = fmaxf(fmaf(lm1, fmaf(-2.f, mm.y, lm1), qq.y), 0.f);
            // zero s2 outside the image (reference zero-pads the 2nd conv)
            int gy = y0 - 4 + rm;
            int gx = x0 - 4 + 2 * pc;
            bool iny = (unsigned)gy < (unsigned)HH;
            s20 = (iny & ((unsigned)gx < (unsigned)WW)) ? s20 : 0.f;
            s21 = (iny & ((unsigned)(gx + 1) < (unsigned)WW)) ? s21 : 0.f;
            *(float2*)&s2s[rm * SW2 + 2 * pc] = make_float2(s20, s21);
            if (wr) {
                int idx = (b * HH + y0 + rm - 4) * WW + x0 + 2 * pc - 4;
                __stcs((__half2*)&g_lm[idx], __floats2half2_rn(lm0, lm1));
            }
        }
    }
    __syncthreads();

    // ---- 3) blur2 on 64x32: sigma + partial sums --------------------------
    const int tx = threadIdx.x, tz = threadIdx.y;
    u64 acc[4];
    blurT<SW2>(s2s, tx, 4 * tz, acc);

    float lsum = 0.f;
#pragma unroll
    for (int oy = 0; oy < 4; oy++) {
        float s0 = sqrtf(fmaxf(__uint_as_float((uint32_t)acc[oy]), 0.f));
        float s1 = sqrtf(fmaxf(__uint_as_float((uint32_t)(acc[oy] >> 32)), 0.f));
        int idx = (b * HH + y0 + 4 * tz + oy) * WW + x0 + 2 * tx;
        __stcs((__half2*)&g_sig[idx], __floats2half2_rn(s0, s1));
        lsum += s0 + s1;
    }

#pragma unroll
    for (int o = 16; o > 0; o >>= 1)
        lsum += __shfl_down_sync(0xFFFFFFFFu, lsum, o);
    if (tx == 0) warpsum[tz] = lsum;
    __syncthreads();
    if (tid == 0) {
        float t = 0.f;
#pragma unroll
        for (int i = 0; i < 8; i++) t += warpsum[i];
        g_part[b * 128 + blockIdx.y * 8 + blockIdx.x] = t;
    }
}

// ---------------------------------------------------------------------------
// Final: prologue re-reduces this batch's 128 partials (L2 hits) -> ms, then
// out = (x - lm) / max(ms, sigma). 8 px / thread, streaming float4 traffic.
// ---------------------------------------------------------------------------
__global__ __launch_bounds__(256) void k_final(const float* __restrict__ x,
                                               float* __restrict__ out) {
    __shared__ float s_w[4];
    __shared__ float s_ms;

    const int b = blockIdx.x >> 7;  // 128 blocks / batch
    if (threadIdx.x < 128) {
        float v = g_part[b * 128 + threadIdx.x];
#pragma unroll
        for (int o = 16; o > 0; o >>= 1)
            v += __shfl_down_sync(0xFFFFFFFFu, v, o);
        if ((threadIdx.x & 31) == 0) s_w[threadIdx.x >> 5] = v;
    }
    __syncthreads();
    if (threadIdx.x == 0)
        s_ms = (s_w[0] + s_w[1] + s_w[2] + s_w[3]) *
               (1.f / ((float)HH * (float)WW));
    __syncthreads();
    const float ms = s_ms;

    const int p = (blockIdx.x & 127) * 2048 + threadIdx.x * 8 + (b << 18);

    uint4 lmu = __ldcs((const uint4*)((const __half*)g_lm + p));
    uint4 sgu = __ldcs((const uint4*)((const __half*)g_sig + p));
    const __half2* lmh = (const __half2*)&lmu;
    const __half2* sgh = (const __half2*)&sgu;

    const float4* xp = (const float4*)(x + (size_t)p * 3);
    float4 xv[6];
#pragma unroll
    for (int i = 0; i < 6; i++) xv[i] = __ldcs(xp + i);

    float lmv[8], inv[8];
#pragma unroll
    for (int i = 0; i < 4; i++) {
        float2 l = __half22float2(lmh[i]);
        float2 s = __half22float2(sgh[i]);
        lmv[2 * i] = l.x;
        lmv[2 * i + 1] = l.y;
        inv[2 * i] = __frcp_rn(fmaxf(ms, s.x));
        inv[2 * i + 1] = __frcp_rn(fmaxf(ms, s.y));
    }

    const float* f = (const float*)xv;
    float4* op = (float4*)(out + (size_t)p * 3);
#pragma unroll
    for (int i = 0; i < 6; i++) {
        float o0 = (f[4 * i + 0] - lmv[(4 * i + 0) / 3]) * inv[(4 * i + 0) / 3];
        float o1 = (f[4 * i + 1] - lmv[(4 * i + 1) / 3]) * inv[(4 * i + 1) / 3];
        float o2 = (f[4 * i + 2] - lmv[(4 * i + 2) / 3]) * inv[(4 * i + 2) / 3];
        float o3 = (f[4 * i + 3] - lmv[(4 * i + 3) / 3]) * inv[(4 * i + 3) / 3];
        __stcs(op + i, make_float4(o0, o1, o2, o3));
    }
}

// ---------------------------------------------------------------------------
extern "C" void kernel_launch(void* const* d_in, const int* in_sizes, int n_in,
                              void* d_out, int out_size) {
    const float* x = (const float*)d_in[0];

    cudaMemcpyToSymbolAsync(c_w, d_in[1], 81 * sizeof(float), 0,
                            cudaMemcpyDeviceToDevice, 0);

    const int smemF = SH1 * SW1 * (int)sizeof(float) +
                      SH1 * SW1 * (int)sizeof(__half) +
                      SH2 * SW2 * (int)sizeof(float);  // 34560 B
    cudaFuncSetAttribute(k_fused, cudaFuncAttributeMaxDynamicSharedMemorySize,
                         smemF);

    dim3 blk(32, 8);
    dim3 grd(WW / TX, HH / TY, BATCH);  // (8, 16, 32) = 4096 CTAs
    k_fused<<<grd, blk, smemF>>>(x);
    k_final<<<BATCH * 128, 256>>>(x, (float*)d_out);
}